// round 11
// baseline (speedup 1.0000x reference)
#include <cuda_runtime.h>
#include <cuda_bf16.h>
#include <cstdint>

#define NN 50000
#define EE 850000
#define KH 4
#define DD 64
#define CC 256    // KH*DD
#define BSTRIDE 264
#define MAXDEG 64   // P(deg>64) ~ >11 sigma for Binom(800K,1/50K)+selfloop

// ---------------- scratch ----------------
__device__ __nv_bfloat16 g_hb[(size_t)NN * CC];
__device__ float g_adst[NN * KH];
__device__ float g_asrc[NN * KH];
__device__ int   g_cnt[NN];      // zero at load; self-cleaned by k_gather each replay
__device__ int   g_csr[(size_t)NN * MAXDEG];

__device__ __forceinline__ unsigned f2tf32(float f) {
    unsigned r;
    asm("cvt.rna.tf32.f32 %0, %1;" : "=r"(r) : "f"(f));
    return r;
}
__device__ __forceinline__ void mma_tf32(float c[4], unsigned a0, unsigned a1,
                                         unsigned a2, unsigned a3,
                                         unsigned b0, unsigned b1) {
    asm volatile(
        "mma.sync.aligned.m16n8k8.row.col.f32.tf32.tf32.f32 "
        "{%0,%1,%2,%3}, {%4,%5,%6,%7}, {%8,%9}, {%0,%1,%2,%3};"
        : "+f"(c[0]), "+f"(c[1]), "+f"(c[2]), "+f"(c[3])
        : "r"(a0), "r"(a1), "r"(a2), "r"(a3), "r"(b0), "r"(b1));
}

// ---------------- K1: tf32 MMA GEMM h = x@W + alpha dots, bf16 h out ----------------
__global__ __launch_bounds__(256, 2) void k_gemm(const float* __restrict__ x,
                                                 const float* __restrict__ W,
                                                 const float* __restrict__ a) {
    extern __shared__ unsigned sm_u[];
    unsigned* Bs = sm_u;                         // [64][264] tf32
    unsigned* Xs = sm_u + 64 * BSTRIDE;          // [64][68]  tf32
    float* ads = (float*)(Xs + 64 * 68);         // [256]
    float* ass = ads + 256;                      // [256]
    __nv_bfloat162* Cs = (__nv_bfloat162*)sm_u;  // reuse Bs region after sync

    const int t = threadIdx.x;
    {
        int k = t >> 6, o = t & 63;
        ads[t] = a[k * 128 + o];
        ass[t] = a[k * 128 + 64 + o];
    }
    for (int idx = t; idx < 64 * 256; idx += 256) {
        int d = idx >> 8, c = idx & 255;
        Bs[d * BSTRIDE + c] = f2tf32(W[(c >> 6) * 4096 + d * 64 + (c & 63)]);
    }
    const int node0 = blockIdx.x * 64;
    for (int idx = t; idx < 64 * 64; idx += 256) {
        int nl = idx >> 6, k = idx & 63;
        int n = node0 + nl;
        Xs[nl * 68 + k] = f2tf32((n < NN) ? x[n * 64 + k] : 0.f);
    }
    __syncthreads();

    const int w = t >> 5, lane = t & 31;
    const int wm = w & 3, wn = w >> 2;
    const int qr = lane >> 2, qc = lane & 3;

    float acc[16][4];
#pragma unroll
    for (int nt = 0; nt < 16; nt++)
#pragma unroll
        for (int j = 0; j < 4; j++) acc[nt][j] = 0.f;

#pragma unroll
    for (int kc = 0; kc < 8; kc++) {
        const int kb = kc * 8;
        const unsigned* Xp = Xs + (wm * 16 + qr) * 68 + kb + qc;
        unsigned a0 = Xp[0];
        unsigned a1 = Xp[8 * 68];
        unsigned a2 = Xp[4];
        unsigned a3 = Xp[8 * 68 + 4];
        const unsigned* Bp = Bs + (kb + qc) * BSTRIDE + wn * 128 + qr;
#pragma unroll
        for (int nt = 0; nt < 16; nt++) {
            unsigned b0 = Bp[nt * 8];
            unsigned b1 = Bp[4 * BSTRIDE + nt * 8];
            mma_tf32(acc[nt], a0, a1, a2, a3, b0, b1);
        }
    }

    // ---- alpha dots from C fragments ----
    float pd0[2] = {0.f, 0.f}, pd1[2] = {0.f, 0.f};
    float ps0[2] = {0.f, 0.f}, ps1[2] = {0.f, 0.f};
#pragma unroll
    for (int nt = 0; nt < 16; nt++) {
        int c = wn * 128 + nt * 8 + qc * 2;
        int hh = nt >> 3;
        float d0 = ads[c], d1 = ads[c + 1], s0 = ass[c], s1 = ass[c + 1];
        pd0[hh] += acc[nt][0] * d0 + acc[nt][1] * d1;
        pd1[hh] += acc[nt][2] * d0 + acc[nt][3] * d1;
        ps0[hh] += acc[nt][0] * s0 + acc[nt][1] * s1;
        ps1[hh] += acc[nt][2] * s0 + acc[nt][3] * s1;
    }
#pragma unroll
    for (int off = 1; off <= 2; off <<= 1) {
#pragma unroll
        for (int hh = 0; hh < 2; hh++) {
            pd0[hh] += __shfl_xor_sync(0xffffffffu, pd0[hh], off);
            pd1[hh] += __shfl_xor_sync(0xffffffffu, pd1[hh], off);
            ps0[hh] += __shfl_xor_sync(0xffffffffu, ps0[hh], off);
            ps1[hh] += __shfl_xor_sync(0xffffffffu, ps1[hh], off);
        }
    }
    if (qc == 0) {
        int n0 = node0 + wm * 16 + qr;
        int n1 = n0 + 8;
        if (n0 < NN) {
#pragma unroll
            for (int hh = 0; hh < 2; hh++) {
                int hk = wn * 2 + hh;
                g_adst[n0 * 4 + hk] = pd0[hh];
                g_asrc[n0 * 4 + hk] = ps0[hh];
            }
        }
        if (n1 < NN) {
#pragma unroll
            for (int hh = 0; hh < 2; hh++) {
                int hk = wn * 2 + hh;
                g_adst[n1 * 4 + hk] = pd1[hh];
                g_asrc[n1 * 4 + hk] = ps1[hh];
            }
        }
    }

    // ---- stage bf16 h in smem, coalesced global store ----
    __syncthreads();
#pragma unroll
    for (int nt = 0; nt < 16; nt++) {
        int col2 = (wn * 128 + nt * 8 + qc * 2) >> 1;
        Cs[(wm * 16 + qr) * 132 + col2]     = __floats2bfloat162_rn(acc[nt][0], acc[nt][1]);
        Cs[(wm * 16 + qr + 8) * 132 + col2] = __floats2bfloat162_rn(acc[nt][2], acc[nt][3]);
    }
    __syncthreads();
    for (int idx = t; idx < 64 * 32; idx += 256) {
        int r = idx >> 5, cg = idx & 31;
        int n = node0 + r;
        if (n < NN)
            *(uint4*)(g_hb + (size_t)n * CC + cg * 8) =
                *(const uint4*)((const char*)Cs + r * 528 + cg * 16);
    }
}

// ---------------- K2: one-pass padded-CSR scatter (side stream) ----------------
__global__ void k_scatter(const int* __restrict__ adj) {
    int e = blockIdx.x * blockDim.x + threadIdx.x;
    if (e < EE) {
        int dst = adj[e];
        int src = adj[EE + e];
        if ((unsigned)dst < NN && (unsigned)src < NN) {
            int p = atomicAdd(&g_cnt[dst], 1);
            if (p < MAXDEG) g_csr[dst * MAXDEG + p] = src;
        }
    }
}

// ---------------- K3: gather, 4-edge direct batch (independent loads), M=0 ----------
__global__ __launch_bounds__(256) void k_gather(const float* __restrict__ x,
                                                const float* __restrict__ ew,
                                                float* __restrict__ out) {
    const int n = (blockIdx.x * blockDim.x + threadIdx.x) >> 5;
    const int lane = threadIdx.x & 31;
    if (n >= NN) return;
    const int k = lane >> 3;

    const float ad = g_adst[n * 4 + k];
    const int beg = n * MAXDEG;
    int deg = g_cnt[n];
    if (lane == 0) g_cnt[n] = 0;  // self-clean for next graph replay
    if (deg > MAXDEG) deg = MAXDEG;
    const int end = beg + deg;

    float a0 = 0.f, a1 = 0.f, a2 = 0.f, a3 = 0.f, a4 = 0.f, a5 = 0.f, a6 = 0.f, a7 = 0.f;
    float den = 0.f;

    const __nv_bfloat16* hbase = g_hb + lane * 8;
    int i = beg;
    for (; i + 4 <= end; i += 4) {
        int s0 = g_csr[i], s1 = g_csr[i + 1], s2 = g_csr[i + 2], s3 = g_csr[i + 3];
        float as0 = g_asrc[s0 * 4 + k];
        float as1 = g_asrc[s1 * 4 + k];
        float as2 = g_asrc[s2 * 4 + k];
        float as3 = g_asrc[s3 * 4 + k];
        uint4 r0 = *(const uint4*)(hbase + (size_t)s0 * CC);
        uint4 r1 = *(const uint4*)(hbase + (size_t)s1 * CC);
        uint4 r2 = *(const uint4*)(hbase + (size_t)s2 * CC);
        uint4 r3 = *(const uint4*)(hbase + (size_t)s3 * CC);

        float t0 = ad + as0, t1 = ad + as1, t2 = ad + as2, t3 = ad + as3;
        float w0 = __expf(fmaxf(t0, 0.01f * t0));
        float w1 = __expf(fmaxf(t1, 0.01f * t1));
        float w2 = __expf(fmaxf(t2, 0.01f * t2));
        float w3 = __expf(fmaxf(t3, 0.01f * t3));
        den += (w0 + w1) + (w2 + w3);

        float2 f;
        f = __bfloat1622float2(*(__nv_bfloat162*)&r0.x); a0 += w0 * f.x; a1 += w0 * f.y;
        f = __bfloat1622float2(*(__nv_bfloat162*)&r0.y); a2 += w0 * f.x; a3 += w0 * f.y;
        f = __bfloat1622float2(*(__nv_bfloat162*)&r0.z); a4 += w0 * f.x; a5 += w0 * f.y;
        f = __bfloat1622float2(*(__nv_bfloat162*)&r0.w); a6 += w0 * f.x; a7 += w0 * f.y;
        f = __bfloat1622float2(*(__nv_bfloat162*)&r1.x); a0 += w1 * f.x; a1 += w1 * f.y;
        f = __bfloat1622float2(*(__nv_bfloat162*)&r1.y); a2 += w1 * f.x; a3 += w1 * f.y;
        f = __bfloat1622float2(*(__nv_bfloat162*)&r1.z); a4 += w1 * f.x; a5 += w1 * f.y;
        f = __bfloat1622float2(*(__nv_bfloat162*)&r1.w); a6 += w1 * f.x; a7 += w1 * f.y;
        f = __bfloat1622float2(*(__nv_bfloat162*)&r2.x); a0 += w2 * f.x; a1 += w2 * f.y;
        f = __bfloat1622float2(*(__nv_bfloat162*)&r2.y); a2 += w2 * f.x; a3 += w2 * f.y;
        f = __bfloat1622float2(*(__nv_bfloat162*)&r2.z); a4 += w2 * f.x; a5 += w2 * f.y;
        f = __bfloat1622float2(*(__nv_bfloat162*)&r2.w); a6 += w2 * f.x; a7 += w2 * f.y;
        f = __bfloat1622float2(*(__nv_bfloat162*)&r3.x); a0 += w3 * f.x; a1 += w3 * f.y;
        f = __bfloat1622float2(*(__nv_bfloat162*)&r3.y); a2 += w3 * f.x; a3 += w3 * f.y;
        f = __bfloat1622float2(*(__nv_bfloat162*)&r3.z); a4 += w3 * f.x; a5 += w3 * f.y;
        f = __bfloat1622float2(*(__nv_bfloat162*)&r3.w); a6 += w3 * f.x; a7 += w3 * f.y;
    }
    for (; i < end; i++) {
        int src = g_csr[i];
        float as = g_asrc[src * 4 + k];
        float s = ad + as;
        float w = __expf(fmaxf(s, 0.01f * s));
        den += w;
        uint4 raw = *(const uint4*)(hbase + (size_t)src * CC);
        float2 f;
        f = __bfloat1622float2(*(__nv_bfloat162*)&raw.x); a0 += w * f.x; a1 += w * f.y;
        f = __bfloat1622float2(*(__nv_bfloat162*)&raw.y); a2 += w * f.x; a3 += w * f.y;
        f = __bfloat1622float2(*(__nv_bfloat162*)&raw.z); a4 += w * f.x; a5 += w * f.y;
        f = __bfloat1622float2(*(__nv_bfloat162*)&raw.w); a6 += w * f.x; a7 += w * f.y;
    }

    const float sc = ew[n * 4 + k] / (den + 1e-8f);
    float v0 = a0 * sc, v1 = a1 * sc, v2 = a2 * sc, v3 = a3 * sc;
    float v4 = a4 * sc, v5 = a5 * sc, v6 = a6 * sc, v7 = a7 * sc;

#pragma unroll
    for (int off = 8; off <= 16; off <<= 1) {
        v0 += __shfl_xor_sync(0xffffffffu, v0, off);
        v1 += __shfl_xor_sync(0xffffffffu, v1, off);
        v2 += __shfl_xor_sync(0xffffffffu, v2, off);
        v3 += __shfl_xor_sync(0xffffffffu, v3, off);
        v4 += __shfl_xor_sync(0xffffffffu, v4, off);
        v5 += __shfl_xor_sync(0xffffffffu, v5, off);
        v6 += __shfl_xor_sync(0xffffffffu, v6, off);
        v7 += __shfl_xor_sync(0xffffffffu, v7, off);
    }

    if (lane < 8) {
        const float4* xp = (const float4*)(x + n * 64 + lane * 8);
        float4 x0 = xp[0];
        float4 x1 = xp[1];
        float4* op = (float4*)(out + n * 64 + lane * 8);
        op[0] = make_float4(v0 + x0.x, v1 + x0.y, v2 + x0.z, v3 + x0.w);
        op[1] = make_float4(v4 + x1.x, v5 + x1.y, v6 + x1.z, v7 + x1.w);
    }
}

// ---------------- launch ----------------
extern "C" void kernel_launch(void* const* d_in, const int* in_sizes, int n_in,
                              void* d_out, int out_size) {
    const float* x   = (const float*)d_in[0];
    const int*   adj = (const int*)d_in[1];
    const float* ew  = (const float*)d_in[2];
    const float* W   = (const float*)d_in[3];
    const float* a   = (const float*)d_in[4];
    float*       out = (float*)d_out;

    const size_t smem = (64 * BSTRIDE + 64 * 68) * sizeof(unsigned) + 512 * sizeof(float);

    static cudaStream_t s2 = nullptr;
    static cudaEvent_t evF = nullptr, evJ = nullptr;
    if (!s2) {
        cudaFuncSetAttribute(k_gemm, cudaFuncAttributeMaxDynamicSharedMemorySize, (int)smem);
        cudaStreamCreateWithFlags(&s2, cudaStreamNonBlocking);
        cudaEventCreateWithFlags(&evF, cudaEventDisableTiming);
        cudaEventCreateWithFlags(&evJ, cudaEventDisableTiming);
    }

    // side stream: one-pass padded-CSR scatter (g_cnt zeroed by previous gather)
    cudaEventRecord(evF, 0);
    cudaStreamWaitEvent(s2, evF, 0);
    k_scatter<<<(EE + 255) / 256, 256, 0, s2>>>(adj);
    cudaEventRecord(evJ, s2);

    // main stream: gemm -> (join) -> gather
    k_gemm<<<(NN + 63) / 64, 256, smem>>>(x, W, a);

    cudaStreamWaitEvent(0, evJ, 0);
    k_gather<<<(NN * 32 + 255) / 256, 256>>>(x, ew, out);
}

// round 12
// speedup vs baseline: 1.8174x; 1.8174x over previous
#include <cuda_runtime.h>
#include <cuda_bf16.h>
#include <cstdint>

#define NN 50000
#define EE 850000
#define KH 4
#define DD 64
#define CC 256    // KH*DD
#define BSTRIDE 264

// ---------------- scratch ----------------
__device__ __nv_bfloat16 g_hb[(size_t)NN * CC];
__device__ float g_adst[NN * KH];
__device__ float g_asrc[NN * KH];
__device__ int   g_cnt[NN];
__device__ int   g_off[NN];
__device__ int   g_cur[NN];
__device__ int   g_csr[EE];
__device__ int   g_admax[KH];
__device__ int   g_asmax[KH];
__device__ int   g_total;

__device__ __forceinline__ int enc_f(float f) {
    int b = __float_as_int(f);
    return b >= 0 ? b : (b ^ 0x7fffffff);
}
__device__ __forceinline__ float dec_f(int v) {
    return v >= 0 ? __int_as_float(v) : __int_as_float(v ^ 0x7fffffff);
}
__device__ __forceinline__ unsigned f2tf32(float f) {
    unsigned r;
    asm("cvt.rna.tf32.f32 %0, %1;" : "=r"(r) : "f"(f));
    return r;
}
__device__ __forceinline__ void mma_tf32(float c[4], unsigned a0, unsigned a1,
                                         unsigned a2, unsigned a3,
                                         unsigned b0, unsigned b1) {
    asm volatile(
        "mma.sync.aligned.m16n8k8.row.col.f32.tf32.tf32.f32 "
        "{%0,%1,%2,%3}, {%4,%5,%6,%7}, {%8,%9}, {%0,%1,%2,%3};"
        : "+f"(c[0]), "+f"(c[1]), "+f"(c[2]), "+f"(c[3])
        : "r"(a0), "r"(a1), "r"(a2), "r"(a3), "r"(b0), "r"(b1));
}

// ---------------- K0: init ----------------
__global__ void k_init() {
    int t = blockIdx.x * blockDim.x + threadIdx.x;
    if (t < NN) g_cnt[t] = 0;
    if (t < KH) { g_admax[t] = (int)0x80000000; g_asmax[t] = (int)0x80000000; }
    if (t == KH) g_total = 0;
}

// ---------------- K1: tf32 MMA GEMM + alpha dots + FUSED per-head alpha max ----------
__global__ __launch_bounds__(256, 2) void k_gemm(const float* __restrict__ x,
                                                 const float* __restrict__ W,
                                                 const float* __restrict__ a) {
    extern __shared__ unsigned sm_u[];
    unsigned* Bs = sm_u;                         // [64][264] tf32
    unsigned* Xs = sm_u + 64 * BSTRIDE;          // [64][68]  tf32
    float* ads = (float*)(Xs + 64 * 68);         // [256]
    float* ass = ads + 256;                      // [256]
    __nv_bfloat162* Cs = (__nv_bfloat162*)sm_u;  // reuse Bs region after sync
    __shared__ int smax[8];                      // [0..3]=dst max, [4..7]=src max

    const int t = threadIdx.x;
    if (t < 8) smax[t] = (int)0x80000000;
    {
        int k = t >> 6, o = t & 63;
        ads[t] = a[k * 128 + o];
        ass[t] = a[k * 128 + 64 + o];
    }
    for (int idx = t; idx < 64 * 256; idx += 256) {
        int d = idx >> 8, c = idx & 255;
        Bs[d * BSTRIDE + c] = f2tf32(W[(c >> 6) * 4096 + d * 64 + (c & 63)]);
    }
    const int node0 = blockIdx.x * 64;
    for (int idx = t; idx < 64 * 64; idx += 256) {
        int nl = idx >> 6, k = idx & 63;
        int n = node0 + nl;
        Xs[nl * 68 + k] = f2tf32((n < NN) ? x[n * 64 + k] : 0.f);
    }
    __syncthreads();

    const int w = t >> 5, lane = t & 31;
    const int wm = w & 3, wn = w >> 2;
    const int qr = lane >> 2, qc = lane & 3;

    float acc[16][4];
#pragma unroll
    for (int nt = 0; nt < 16; nt++)
#pragma unroll
        for (int j = 0; j < 4; j++) acc[nt][j] = 0.f;

#pragma unroll
    for (int kc = 0; kc < 8; kc++) {
        const int kb = kc * 8;
        const unsigned* Xp = Xs + (wm * 16 + qr) * 68 + kb + qc;
        unsigned a0 = Xp[0];
        unsigned a1 = Xp[8 * 68];
        unsigned a2 = Xp[4];
        unsigned a3 = Xp[8 * 68 + 4];
        const unsigned* Bp = Bs + (kb + qc) * BSTRIDE + wn * 128 + qr;
#pragma unroll
        for (int nt = 0; nt < 16; nt++) {
            unsigned b0 = Bp[nt * 8];
            unsigned b1 = Bp[4 * BSTRIDE + nt * 8];
            mma_tf32(acc[nt], a0, a1, a2, a3, b0, b1);
        }
    }

    // ---- alpha dots from C fragments ----
    float pd0[2] = {0.f, 0.f}, pd1[2] = {0.f, 0.f};
    float ps0[2] = {0.f, 0.f}, ps1[2] = {0.f, 0.f};
#pragma unroll
    for (int nt = 0; nt < 16; nt++) {
        int c = wn * 128 + nt * 8 + qc * 2;
        int hh = nt >> 3;
        float d0 = ads[c], d1 = ads[c + 1], s0 = ass[c], s1 = ass[c + 1];
        pd0[hh] += acc[nt][0] * d0 + acc[nt][1] * d1;
        pd1[hh] += acc[nt][2] * d0 + acc[nt][3] * d1;
        ps0[hh] += acc[nt][0] * s0 + acc[nt][1] * s1;
        ps1[hh] += acc[nt][2] * s0 + acc[nt][3] * s1;
    }
#pragma unroll
    for (int off = 1; off <= 2; off <<= 1) {
#pragma unroll
        for (int hh = 0; hh < 2; hh++) {
            pd0[hh] += __shfl_xor_sync(0xffffffffu, pd0[hh], off);
            pd1[hh] += __shfl_xor_sync(0xffffffffu, pd1[hh], off);
            ps0[hh] += __shfl_xor_sync(0xffffffffu, ps0[hh], off);
            ps1[hh] += __shfl_xor_sync(0xffffffffu, ps1[hh], off);
        }
    }
    if (qc == 0) {
        int n0 = node0 + wm * 16 + qr;
        int n1 = n0 + 8;
        if (n0 < NN) {
#pragma unroll
            for (int hh = 0; hh < 2; hh++) {
                int hk = wn * 2 + hh;
                g_adst[n0 * 4 + hk] = pd0[hh];
                g_asrc[n0 * 4 + hk] = ps0[hh];
                atomicMax(&smax[hk], enc_f(pd0[hh]));
                atomicMax(&smax[4 + hk], enc_f(ps0[hh]));
            }
        }
        if (n1 < NN) {
#pragma unroll
            for (int hh = 0; hh < 2; hh++) {
                int hk = wn * 2 + hh;
                g_adst[n1 * 4 + hk] = pd1[hh];
                g_asrc[n1 * 4 + hk] = ps1[hh];
                atomicMax(&smax[hk], enc_f(pd1[hh]));
                atomicMax(&smax[4 + hk], enc_f(ps1[hh]));
            }
        }
    }

    // ---- stage bf16 h in smem, coalesced global store; flush block maxima ----
    __syncthreads();
#pragma unroll
    for (int nt = 0; nt < 16; nt++) {
        int col2 = (wn * 128 + nt * 8 + qc * 2) >> 1;
        Cs[(wm * 16 + qr) * 132 + col2]     = __floats2bfloat162_rn(acc[nt][0], acc[nt][1]);
        Cs[(wm * 16 + qr + 8) * 132 + col2] = __floats2bfloat162_rn(acc[nt][2], acc[nt][3]);
    }
    __syncthreads();
    if (t < 4)           atomicMax(&g_admax[t], smax[t]);
    else if (t < 8)      atomicMax(&g_asmax[t - 4], smax[t]);
    for (int idx = t; idx < 64 * 32; idx += 256) {
        int r = idx >> 5, cg = idx & 31;
        int n = node0 + r;
        if (n < NN)
            *(uint4*)(g_hb + (size_t)n * CC + cg * 8) =
                *(const uint4*)((const char*)Cs + r * 528 + cg * 16);
    }
}

// ---------------- K2a: degree count, 4 edges/thread (side stream) --------------
__global__ void k_cnt(const int* __restrict__ adj) {
    int e4 = (blockIdx.x * blockDim.x + threadIdx.x) * 4;
    if (e4 + 3 < EE) {
        int4 d = *(const int4*)(adj + e4);
        if ((unsigned)d.x < NN) atomicAdd(&g_cnt[d.x], 1);
        if ((unsigned)d.y < NN) atomicAdd(&g_cnt[d.y], 1);
        if ((unsigned)d.z < NN) atomicAdd(&g_cnt[d.z], 1);
        if ((unsigned)d.w < NN) atomicAdd(&g_cnt[d.w], 1);
    } else {
        for (int e = e4; e < EE; e++) {
            int dst = adj[e];
            if ((unsigned)dst < NN) atomicAdd(&g_cnt[dst], 1);
        }
    }
}

// ---------------- K2b: parallel bucket allocation ----------------
__global__ void k_alloc() {
    const int n = blockIdx.x * blockDim.x + threadIdx.x;
    const int lane = threadIdx.x & 31;
    int c = (n < NN) ? g_cnt[n] : 0;
    int incl = c;
#pragma unroll
    for (int off = 1; off < 32; off <<= 1) {
        int v = __shfl_up_sync(0xffffffffu, incl, off);
        if (lane >= off) incl += v;
    }
    int wtotal = __shfl_sync(0xffffffffu, incl, 31);
    int base = 0;
    if (lane == 31) base = atomicAdd(&g_total, wtotal);
    base = __shfl_sync(0xffffffffu, base, 31);
    if (n < NN) {
        int off = base + incl - c;
        g_off[n] = off;
        g_cur[n] = off;
    }
}

// ---------------- K2c: scatter, 4 edges/thread (side stream) ----------------
__global__ void k_scatter(const int* __restrict__ adj) {
    int e4 = (blockIdx.x * blockDim.x + threadIdx.x) * 4;
    if (e4 + 3 < EE) {
        int4 d = *(const int4*)(adj + e4);
        int4 s = *(const int4*)(adj + EE + e4);
        int p0 = ((unsigned)d.x < NN) ? atomicAdd(&g_cur[d.x], 1) : -1;
        int p1 = ((unsigned)d.y < NN) ? atomicAdd(&g_cur[d.y], 1) : -1;
        int p2 = ((unsigned)d.z < NN) ? atomicAdd(&g_cur[d.z], 1) : -1;
        int p3 = ((unsigned)d.w < NN) ? atomicAdd(&g_cur[d.w], 1) : -1;
        if ((unsigned)p0 < EE) g_csr[p0] = s.x;
        if ((unsigned)p1 < EE) g_csr[p1] = s.y;
        if ((unsigned)p2 < EE) g_csr[p2] = s.z;
        if ((unsigned)p3 < EE) g_csr[p3] = s.w;
    } else {
        for (int e = e4; e < EE; e++) {
            int dst = adj[e];
            int src = adj[EE + e];
            if ((unsigned)dst < NN && (unsigned)src < NN) {
                int p = atomicAdd(&g_cur[dst], 1);
                if ((unsigned)p < EE) g_csr[p] = src;
            }
        }
    }
}

// ---------------- K3: gather, 4-edge batched, M-shifted softmax ----------------
__global__ __launch_bounds__(256) void k_gather(const float* __restrict__ x,
                                                const float* __restrict__ ew,
                                                float* __restrict__ out) {
    const int n = (blockIdx.x * blockDim.x + threadIdx.x) >> 5;
    const int lane = threadIdx.x & 31;
    if (n >= NN) return;
    const int k = lane >> 3;

    float M = dec_f(g_admax[k]) + dec_f(g_asmax[k]);
    M = fmaxf(M, 0.01f * M);
    const float ad = g_adst[n * 4 + k];
    const int beg = g_off[n];
    const int end = beg + g_cnt[n];

    float a0 = 0.f, a1 = 0.f, a2 = 0.f, a3 = 0.f, a4 = 0.f, a5 = 0.f, a6 = 0.f, a7 = 0.f;
    float den = 0.f;

    const __nv_bfloat16* hbase = g_hb + lane * 8;
    int i = beg;
    for (; i + 4 <= end; i += 4) {
        int s0 = g_csr[i], s1 = g_csr[i + 1], s2 = g_csr[i + 2], s3 = g_csr[i + 3];
        float as0 = g_asrc[s0 * 4 + k];
        float as1 = g_asrc[s1 * 4 + k];
        float as2 = g_asrc[s2 * 4 + k];
        float as3 = g_asrc[s3 * 4 + k];
        uint4 r0 = *(const uint4*)(hbase + (size_t)s0 * CC);
        uint4 r1 = *(const uint4*)(hbase + (size_t)s1 * CC);
        uint4 r2 = *(const uint4*)(hbase + (size_t)s2 * CC);
        uint4 r3 = *(const uint4*)(hbase + (size_t)s3 * CC);

        float t0 = ad + as0, t1 = ad + as1, t2 = ad + as2, t3 = ad + as3;
        float w0 = __expf(fmaxf(t0, 0.01f * t0) - M);
        float w1 = __expf(fmaxf(t1, 0.01f * t1) - M);
        float w2 = __expf(fmaxf(t2, 0.01f * t2) - M);
        float w3 = __expf(fmaxf(t3, 0.01f * t3) - M);
        den += (w0 + w1) + (w2 + w3);

        float2 f;
        f = __bfloat1622float2(*(__nv_bfloat162*)&r0.x); a0 += w0 * f.x; a1 += w0 * f.y;
        f = __bfloat1622float2(*(__nv_bfloat162*)&r0.y); a2 += w0 * f.x; a3 += w0 * f.y;
        f = __bfloat1622float2(*(__nv_bfloat162*)&r0.z); a4 += w0 * f.x; a5 += w0 * f.y;
        f = __bfloat1622float2(*(__nv_bfloat162*)&r0.w); a6 += w0 * f.x; a7 += w0 * f.y;
        f = __bfloat1622float2(*(__nv_bfloat162*)&r1.x); a0 += w1 * f.x; a1 += w1 * f.y;
        f = __bfloat1622float2(*(__nv_bfloat162*)&r1.y); a2 += w1 * f.x; a3 += w1 * f.y;
        f = __bfloat1622float2(*(__nv_bfloat162*)&r1.z); a4 += w1 * f.x; a5 += w1 * f.y;
        f = __bfloat1622float2(*(__nv_bfloat162*)&r1.w); a6 += w1 * f.x; a7 += w1 * f.y;
        f = __bfloat1622float2(*(__nv_bfloat162*)&r2.x); a0 += w2 * f.x; a1 += w2 * f.y;
        f = __bfloat1622float2(*(__nv_bfloat162*)&r2.y); a2 += w2 * f.x; a3 += w2 * f.y;
        f = __bfloat1622float2(*(__nv_bfloat162*)&r2.z); a4 += w2 * f.x; a5 += w2 * f.y;
        f = __bfloat1622float2(*(__nv_bfloat162*)&r2.w); a6 += w2 * f.x; a7 += w2 * f.y;
        f = __bfloat1622float2(*(__nv_bfloat162*)&r3.x); a0 += w3 * f.x; a1 += w3 * f.y;
        f = __bfloat1622float2(*(__nv_bfloat162*)&r3.y); a2 += w3 * f.x; a3 += w3 * f.y;
        f = __bfloat1622float2(*(__nv_bfloat162*)&r3.z); a4 += w3 * f.x; a5 += w3 * f.y;
        f = __bfloat1622float2(*(__nv_bfloat162*)&r3.w); a6 += w3 * f.x; a7 += w3 * f.y;
    }
    for (; i < end; i++) {
        int src = g_csr[i];
        float as = g_asrc[src * 4 + k];
        float s = ad + as;
        float w = __expf(fmaxf(s, 0.01f * s) - M);
        den += w;
        uint4 raw = *(const uint4*)(hbase + (size_t)src * CC);
        float2 f;
        f = __bfloat1622float2(*(__nv_bfloat162*)&raw.x); a0 += w * f.x; a1 += w * f.y;
        f = __bfloat1622float2(*(__nv_bfloat162*)&raw.y); a2 += w * f.x; a3 += w * f.y;
        f = __bfloat1622float2(*(__nv_bfloat162*)&raw.z); a4 += w * f.x; a5 += w * f.y;
        f = __bfloat1622float2(*(__nv_bfloat162*)&raw.w); a6 += w * f.x; a7 += w * f.y;
    }

    const float sc = ew[n * 4 + k] / (den + 1e-8f);
    float v0 = a0 * sc, v1 = a1 * sc, v2 = a2 * sc, v3 = a3 * sc;
    float v4 = a4 * sc, v5 = a5 * sc, v6 = a6 * sc, v7 = a7 * sc;

#pragma unroll
    for (int off = 8; off <= 16; off <<= 1) {
        v0 += __shfl_xor_sync(0xffffffffu, v0, off);
        v1 += __shfl_xor_sync(0xffffffffu, v1, off);
        v2 += __shfl_xor_sync(0xffffffffu, v2, off);
        v3 += __shfl_xor_sync(0xffffffffu, v3, off);
        v4 += __shfl_xor_sync(0xffffffffu, v4, off);
        v5 += __shfl_xor_sync(0xffffffffu, v5, off);
        v6 += __shfl_xor_sync(0xffffffffu, v6, off);
        v7 += __shfl_xor_sync(0xffffffffu, v7, off);
    }

    if (lane < 8) {
        const float4* xp = (const float4*)(x + n * 64 + lane * 8);
        float4 x0 = xp[0];
        float4 x1 = xp[1];
        float4* op = (float4*)(out + n * 64 + lane * 8);
        op[0] = make_float4(v0 + x0.x, v1 + x0.y, v2 + x0.z, v3 + x0.w);
        op[1] = make_float4(v4 + x1.x, v5 + x1.y, v6 + x1.z, v7 + x1.w);
    }
}

// ---------------- launch ----------------
extern "C" void kernel_launch(void* const* d_in, const int* in_sizes, int n_in,
                              void* d_out, int out_size) {
    const float* x   = (const float*)d_in[0];
    const int*   adj = (const int*)d_in[1];
    const float* ew  = (const float*)d_in[2];
    const float* W   = (const float*)d_in[3];
    const float* a   = (const float*)d_in[4];
    float*       out = (float*)d_out;

    const size_t smem = (64 * BSTRIDE + 64 * 68) * sizeof(unsigned) + 512 * sizeof(float);

    static cudaStream_t s2 = nullptr;
    static cudaEvent_t evF = nullptr, evJ = nullptr;
    if (!s2) {
        cudaFuncSetAttribute(k_gemm, cudaFuncAttributeMaxDynamicSharedMemorySize, (int)smem);
        cudaStreamCreateWithFlags(&s2, cudaStreamNonBlocking);
        cudaEventCreateWithFlags(&evF, cudaEventDisableTiming);
        cudaEventCreateWithFlags(&evJ, cudaEventDisableTiming);
    }

    k_init<<<(NN + 255) / 256, 256>>>();
    cudaEventRecord(evF, 0);
    cudaStreamWaitEvent(s2, evF, 0);

    const int E4 = (EE / 4 + 255) / 256;
    k_cnt<<<E4, 256, 0, s2>>>(adj);
    k_alloc<<<(NN + 255) / 256, 256, 0, s2>>>();
    k_scatter<<<E4, 256, 0, s2>>>(adj);
    cudaEventRecord(evJ, s2);

    k_gemm<<<(NN + 63) / 64, 256, smem>>>(x, W, a);

    cudaStreamWaitEvent(0, evJ, 0);
    k_gather<<<(NN * 32 + 255) / 256, 256>>>(x, ew, out);
}

// round 15
// speedup vs baseline: 1.8710x; 1.0295x over previous
#include <cuda_runtime.h>
#include <cuda_bf16.h>
#include <cstdint>

#define NN 50000
#define EE 850000
#define KH 4
#define DD 64
#define CC 256    // KH*DD
#define BSTRIDE 264

// ---------------- scratch ----------------
__device__ __nv_bfloat16 g_hb[(size_t)NN * CC];
__device__ float g_adst[NN * KH];
__device__ float g_asrc[NN * KH];
__device__ int   g_cnt[NN];
__device__ int   g_off[NN];
__device__ int   g_cur[NN];
__device__ int   g_csr[EE];
__device__ int   g_admax[KH];
__device__ int   g_asmax[KH];
__device__ int   g_total;

__device__ __forceinline__ int enc_f(float f) {
    int b = __float_as_int(f);
    return b >= 0 ? b : (b ^ 0x7fffffff);
}
__device__ __forceinline__ float dec_f(int v) {
    return v >= 0 ? __int_as_float(v) : __int_as_float(v ^ 0x7fffffff);
}
__device__ __forceinline__ unsigned f2tf32(float f) {
    unsigned r;
    asm("cvt.rna.tf32.f32 %0, %1;" : "=r"(r) : "f"(f));
    return r;
}
__device__ __forceinline__ void mma_tf32(float c[4], unsigned a0, unsigned a1,
                                         unsigned a2, unsigned a3,
                                         unsigned b0, unsigned b1) {
    asm volatile(
        "mma.sync.aligned.m16n8k8.row.col.f32.tf32.tf32.f32 "
        "{%0,%1,%2,%3}, {%4,%5,%6,%7}, {%8,%9}, {%0,%1,%2,%3};"
        : "+f"(c[0]), "+f"(c[1]), "+f"(c[2]), "+f"(c[3])
        : "r"(a0), "r"(a1), "r"(a2), "r"(a3), "r"(b0), "r"(b1));
}

// bf16x2 (packed in u32) -> f32x2 (packed in u64), exact: f32 = bf16 << 16
#define BF2_TO_F32X2(v64, r32) do {                                   \
    unsigned _lo = (r32) << 16;                                       \
    unsigned _hi = (r32) & 0xffff0000u;                               \
    asm("mov.b64 %0, {%1, %2};" : "=l"(v64) : "r"(_lo), "r"(_hi));    \
} while (0)
#define FMA_F32X2(acc64, h64, w64) \
    asm("fma.rn.f32x2 %0, %1, %2, %0;" : "+l"(acc64) : "l"(h64), "l"(w64))
#define PACK2(v64, w32) \
    asm("mov.b64 %0, {%1, %1};" : "=l"(v64) : "r"(w32))

// ---------------- K0: init ----------------
__global__ void k_init() {
    int t = blockIdx.x * blockDim.x + threadIdx.x;
    if (t < NN) g_cnt[t] = 0;
    if (t < KH) { g_admax[t] = (int)0x80000000; g_asmax[t] = (int)0x80000000; }
    if (t == KH) g_total = 0;
}

// ---------------- K1: tf32 MMA GEMM + alpha dots + fused per-head alpha max ----------
__global__ __launch_bounds__(256, 2) void k_gemm(const float* __restrict__ x,
                                                 const float* __restrict__ W,
                                                 const float* __restrict__ a) {
    extern __shared__ unsigned sm_u[];
    unsigned* Bs = sm_u;                         // [64][264] tf32
    unsigned* Xs = sm_u + 64 * BSTRIDE;          // [64][68]  tf32
    float* ads = (float*)(Xs + 64 * 68);         // [256]
    float* ass = ads + 256;                      // [256]
    __nv_bfloat162* Cs = (__nv_bfloat162*)sm_u;  // reuse Bs region after sync
    __shared__ int smax[8];

    const int t = threadIdx.x;
    if (t < 8) smax[t] = (int)0x80000000;
    {
        int k = t >> 6, o = t & 63;
        ads[t] = a[k * 128 + o];
        ass[t] = a[k * 128 + 64 + o];
    }
    for (int idx = t; idx < 64 * 256; idx += 256) {
        int d = idx >> 8, c = idx & 255;
        Bs[d * BSTRIDE + c] = f2tf32(W[(c >> 6) * 4096 + d * 64 + (c & 63)]);
    }
    const int node0 = blockIdx.x * 64;
    for (int idx = t; idx < 64 * 64; idx += 256) {
        int nl = idx >> 6, k = idx & 63;
        int n = node0 + nl;
        Xs[nl * 68 + k] = f2tf32((n < NN) ? x[n * 64 + k] : 0.f);
    }
    __syncthreads();

    const int w = t >> 5, lane = t & 31;
    const int wm = w & 3, wn = w >> 2;
    const int qr = lane >> 2, qc = lane & 3;

    float acc[16][4];
#pragma unroll
    for (int nt = 0; nt < 16; nt++)
#pragma unroll
        for (int j = 0; j < 4; j++) acc[nt][j] = 0.f;

#pragma unroll
    for (int kc = 0; kc < 8; kc++) {
        const int kb = kc * 8;
        const unsigned* Xp = Xs + (wm * 16 + qr) * 68 + kb + qc;
        unsigned a0 = Xp[0];
        unsigned a1 = Xp[8 * 68];
        unsigned a2 = Xp[4];
        unsigned a3 = Xp[8 * 68 + 4];
        const unsigned* Bp = Bs + (kb + qc) * BSTRIDE + wn * 128 + qr;
#pragma unroll
        for (int nt = 0; nt < 16; nt++) {
            unsigned b0 = Bp[nt * 8];
            unsigned b1 = Bp[4 * BSTRIDE + nt * 8];
            mma_tf32(acc[nt], a0, a1, a2, a3, b0, b1);
        }
    }

    float pd0[2] = {0.f, 0.f}, pd1[2] = {0.f, 0.f};
    float ps0[2] = {0.f, 0.f}, ps1[2] = {0.f, 0.f};
#pragma unroll
    for (int nt = 0; nt < 16; nt++) {
        int c = wn * 128 + nt * 8 + qc * 2;
        int hh = nt >> 3;
        float d0 = ads[c], d1 = ads[c + 1], s0 = ass[c], s1 = ass[c + 1];
        pd0[hh] += acc[nt][0] * d0 + acc[nt][1] * d1;
        pd1[hh] += acc[nt][2] * d0 + acc[nt][3] * d1;
        ps0[hh] += acc[nt][0] * s0 + acc[nt][1] * s1;
        ps1[hh] += acc[nt][2] * s0 + acc[nt][3] * s1;
    }
#pragma unroll
    for (int off = 1; off <= 2; off <<= 1) {
#pragma unroll
        for (int hh = 0; hh < 2; hh++) {
            pd0[hh] += __shfl_xor_sync(0xffffffffu, pd0[hh], off);
            pd1[hh] += __shfl_xor_sync(0xffffffffu, pd1[hh], off);
            ps0[hh] += __shfl_xor_sync(0xffffffffu, ps0[hh], off);
            ps1[hh] += __shfl_xor_sync(0xffffffffu, ps1[hh], off);
        }
    }
    if (qc == 0) {
        int n0 = node0 + wm * 16 + qr;
        int n1 = n0 + 8;
        if (n0 < NN) {
#pragma unroll
            for (int hh = 0; hh < 2; hh++) {
                int hk = wn * 2 + hh;
                g_adst[n0 * 4 + hk] = pd0[hh];
                g_asrc[n0 * 4 + hk] = ps0[hh];
                atomicMax(&smax[hk], enc_f(pd0[hh]));
                atomicMax(&smax[4 + hk], enc_f(ps0[hh]));
            }
        }
        if (n1 < NN) {
#pragma unroll
            for (int hh = 0; hh < 2; hh++) {
                int hk = wn * 2 + hh;
                g_adst[n1 * 4 + hk] = pd1[hh];
                g_asrc[n1 * 4 + hk] = ps1[hh];
                atomicMax(&smax[hk], enc_f(pd1[hh]));
                atomicMax(&smax[4 + hk], enc_f(ps1[hh]));
            }
        }
    }

    __syncthreads();
#pragma unroll
    for (int nt = 0; nt < 16; nt++) {
        int col2 = (wn * 128 + nt * 8 + qc * 2) >> 1;
        Cs[(wm * 16 + qr) * 132 + col2]     = __floats2bfloat162_rn(acc[nt][0], acc[nt][1]);
        Cs[(wm * 16 + qr + 8) * 132 + col2] = __floats2bfloat162_rn(acc[nt][2], acc[nt][3]);
    }
    __syncthreads();
    if (t < 4)           atomicMax(&g_admax[t], smax[t]);
    else if (t < 8)      atomicMax(&g_asmax[t - 4], smax[t]);
    for (int idx = t; idx < 64 * 32; idx += 256) {
        int r = idx >> 5, cg = idx & 31;
        int n = node0 + r;
        if (n < NN)
            *(uint4*)(g_hb + (size_t)n * CC + cg * 8) =
                *(const uint4*)((const char*)Cs + r * 528 + cg * 16);
    }
}

// ---------------- K2a: degree count, 1 edge/thread ----------------
__global__ void k_cnt(const int* __restrict__ adj) {
    int e = blockIdx.x * blockDim.x + threadIdx.x;
    if (e < EE) {
        int dst = adj[e];
        if ((unsigned)dst < NN) atomicAdd(&g_cnt[dst], 1);
    }
}

// ---------------- K2b: parallel bucket allocation ----------------
__global__ void k_alloc() {
    const int n = blockIdx.x * blockDim.x + threadIdx.x;
    const int lane = threadIdx.x & 31;
    int c = (n < NN) ? g_cnt[n] : 0;
    int incl = c;
#pragma unroll
    for (int off = 1; off < 32; off <<= 1) {
        int v = __shfl_up_sync(0xffffffffu, incl, off);
        if (lane >= off) incl += v;
    }
    int wtotal = __shfl_sync(0xffffffffu, incl, 31);
    int base = 0;
    if (lane == 31) base = atomicAdd(&g_total, wtotal);
    base = __shfl_sync(0xffffffffu, base, 31);
    if (n < NN) {
        int off = base + incl - c;
        g_off[n] = off;
        g_cur[n] = off;
    }
}

// ---------------- K2c: scatter, 1 edge/thread ----------------
__global__ void k_scatter(const int* __restrict__ adj) {
    int e = blockIdx.x * blockDim.x + threadIdx.x;
    if (e < EE) {
        int dst = adj[e];
        int src = adj[EE + e];
        if ((unsigned)dst < NN && (unsigned)src < NN) {
            int p = atomicAdd(&g_cur[dst], 1);
            if ((unsigned)p < EE) g_csr[p] = src;
        }
    }
}

// ---------------- K3: gather, 4-edge batch, packed f32x2 FMA accumulate ----------------
__global__ __launch_bounds__(256) void k_gather(const float* __restrict__ x,
                                                const float* __restrict__ ew,
                                                float* __restrict__ out) {
    const int n = (blockIdx.x * blockDim.x + threadIdx.x) >> 5;
    const int lane = threadIdx.x & 31;
    if (n >= NN) return;
    const int k = lane >> 3;

    float M = dec_f(g_admax[k]) + dec_f(g_asmax[k]);
    M = fmaxf(M, 0.01f * M);
    const float ad = g_adst[n * 4 + k];
    const int beg = g_off[n];
    const int end = beg + g_cnt[n];

    unsigned long long A0 = 0ull, A1 = 0ull, A2 = 0ull, A3 = 0ull;  // 8 f32 accumulators
    float den = 0.f;

    const __nv_bfloat16* hbase = g_hb + lane * 8;
    int i = beg;
    for (; i + 4 <= end; i += 4) {
        int s0 = g_csr[i], s1 = g_csr[i + 1], s2 = g_csr[i + 2], s3 = g_csr[i + 3];
        float as0 = g_asrc[s0 * 4 + k];
        float as1 = g_asrc[s1 * 4 + k];
        float as2 = g_asrc[s2 * 4 + k];
        float as3 = g_asrc[s3 * 4 + k];
        uint4 r0 = *(const uint4*)(hbase + (size_t)s0 * CC);
        uint4 r1 = *(const uint4*)(hbase + (size_t)s1 * CC);
        uint4 r2 = *(const uint4*)(hbase + (size_t)s2 * CC);
        uint4 r3 = *(const uint4*)(hbase + (size_t)s3 * CC);

        float t0 = ad + as0, t1 = ad + as1, t2 = ad + as2, t3 = ad + as3;
        float w0 = __expf(fmaxf(t0, 0.01f * t0) - M);
        float w1 = __expf(fmaxf(t1, 0.01f * t1) - M);
        float w2 = __expf(fmaxf(t2, 0.01f * t2) - M);
        float w3 = __expf(fmaxf(t3, 0.01f * t3) - M);
        den += (w0 + w1) + (w2 + w3);

        unsigned long long wp, hv;
        PACK2(wp, __float_as_uint(w0));
        BF2_TO_F32X2(hv, r0.x); FMA_F32X2(A0, hv, wp);
        BF2_TO_F32X2(hv, r0.y); FMA_F32X2(A1, hv, wp);
        BF2_TO_F32X2(hv, r0.z); FMA_F32X2(A2, hv, wp);
        BF2_TO_F32X2(hv, r0.w); FMA_F32X2(A3, hv, wp);
        PACK2(wp, __float_as_uint(w1));
        BF2_TO_F32X2(hv, r1.x); FMA_F32X2(A0, hv, wp);
        BF2_TO_F32X2(hv, r1.y); FMA_F32X2(A1, hv, wp);
        BF2_TO_F32X2(hv, r1.z); FMA_F32X2(A2, hv, wp);
        BF2_TO_F32X2(hv, r1.w); FMA_F32X2(A3, hv, wp);
        PACK2(wp, __float_as_uint(w2));
        BF2_TO_F32X2(hv, r2.x); FMA_F32X2(A0, hv, wp);
        BF2_TO_F32X2(hv, r2.y); FMA_F32X2(A1, hv, wp);
        BF2_TO_F32X2(hv, r2.z); FMA_F32X2(A2, hv, wp);
        BF2_TO_F32X2(hv, r2.w); FMA_F32X2(A3, hv, wp);
        PACK2(wp, __float_as_uint(w3));
        BF2_TO_F32X2(hv, r3.x); FMA_F32X2(A0, hv, wp);
        BF2_TO_F32X2(hv, r3.y); FMA_F32X2(A1, hv, wp);
        BF2_TO_F32X2(hv, r3.z); FMA_F32X2(A2, hv, wp);
        BF2_TO_F32X2(hv, r3.w); FMA_F32X2(A3, hv, wp);
    }
    for (; i < end; i++) {
        int src = g_csr[i];
        float as = g_asrc[src * 4 + k];
        float s = ad + as;
        float w = __expf(fmaxf(s, 0.01f * s) - M);
        den += w;
        uint4 raw = *(const uint4*)(hbase + (size_t)src * CC);
        unsigned long long wp, hv;
        PACK2(wp, __float_as_uint(w));
        BF2_TO_F32X2(hv, raw.x); FMA_F32X2(A0, hv, wp);
        BF2_TO_F32X2(hv, raw.y); FMA_F32X2(A1, hv, wp);
        BF2_TO_F32X2(hv, raw.z); FMA_F32X2(A2, hv, wp);
        BF2_TO_F32X2(hv, raw.w); FMA_F32X2(A3, hv, wp);
    }

    // unpack accumulators
    unsigned u0, u1;
    float v0, v1, v2, v3, v4, v5, v6, v7;
    asm("mov.b64 {%0,%1}, %2;" : "=r"(u0), "=r"(u1) : "l"(A0));
    v0 = __uint_as_float(u0); v1 = __uint_as_float(u1);
    asm("mov.b64 {%0,%1}, %2;" : "=r"(u0), "=r"(u1) : "l"(A1));
    v2 = __uint_as_float(u0); v3 = __uint_as_float(u1);
    asm("mov.b64 {%0,%1}, %2;" : "=r"(u0), "=r"(u1) : "l"(A2));
    v4 = __uint_as_float(u0); v5 = __uint_as_float(u1);
    asm("mov.b64 {%0,%1}, %2;" : "=r"(u0), "=r"(u1) : "l"(A3));
    v6 = __uint_as_float(u0); v7 = __uint_as_float(u1);

    const float sc = ew[n * 4 + k] / (den + 1e-8f);
    v0 *= sc; v1 *= sc; v2 *= sc; v3 *= sc;
    v4 *= sc; v5 *= sc; v6 *= sc; v7 *= sc;

#pragma unroll
    for (int off = 8; off <= 16; off <<= 1) {
        v0 += __shfl_xor_sync(0xffffffffu, v0, off);
        v1 += __shfl_xor_sync(0xffffffffu, v1, off);
        v2 += __shfl_xor_sync(0xffffffffu, v2, off);
        v3 += __shfl_xor_sync(0xffffffffu, v3, off);
        v4 += __shfl_xor_sync(0xffffffffu, v4, off);
        v5 += __shfl_xor_sync(0xffffffffu, v5, off);
        v6 += __shfl_xor_sync(0xffffffffu, v6, off);
        v7 += __shfl_xor_sync(0xffffffffu, v7, off);
    }

    if (lane < 8) {
        const float4* xp = (const float4*)(x + n * 64 + lane * 8);
        float4 x0 = xp[0];
        float4 x1 = xp[1];
        float4* op = (float4*)(out + n * 64 + lane * 8);
        op[0] = make_float4(v0 + x0.x, v1 + x0.y, v2 + x0.z, v3 + x0.w);
        op[1] = make_float4(v4 + x1.x, v5 + x1.y, v6 + x1.z, v7 + x1.w);
    }
}

// ---------------- launch ----------------
extern "C" void kernel_launch(void* const* d_in, const int* in_sizes, int n_in,
                              void* d_out, int out_size) {
    const float* x   = (const float*)d_in[0];
    const int*   adj = (const int*)d_in[1];
    const float* ew  = (const float*)d_in[2];
    const float* W   = (const float*)d_in[3];
    const float* a   = (const float*)d_in[4];
    float*       out = (float*)d_out;

    const size_t smem = (64 * BSTRIDE + 64 * 68) * sizeof(unsigned) + 512 * sizeof(float);

    static cudaStream_t s2 = nullptr;
    static cudaEvent_t evF = nullptr, evJ = nullptr;
    if (!s2) {
        cudaFuncSetAttribute(k_gemm, cudaFuncAttributeMaxDynamicSharedMemorySize, (int)smem);
        cudaStreamCreateWithFlags(&s2, cudaStreamNonBlocking);
        cudaEventCreateWithFlags(&evF, cudaEventDisableTiming);
        cudaEventCreateWithFlags(&evJ, cudaEventDisableTiming);
    }

    k_init<<<(NN + 255) / 256, 256>>>();
    cudaEventRecord(evF, 0);
    cudaStreamWaitEvent(s2, evF, 0);

    k_cnt<<<(EE + 255) / 256, 256, 0, s2>>>(adj);
    k_alloc<<<(NN + 255) / 256, 256, 0, s2>>>();
    k_scatter<<<(EE + 255) / 256, 256, 0, s2>>>(adj);
    cudaEventRecord(evJ, s2);

    k_gemm<<<(NN + 63) / 64, 256, smem>>>(x, W, a);

    cudaStreamWaitEvent(0, evJ, 0);
    k_gather<<<(NN * 32 + 255) / 256, 256>>>(x, ew, out);
}